// round 16
// baseline (speedup 1.0000x reference)
#include <cuda_runtime.h>
#include <cuda_fp16.h>
#include <cstdint>

#define NN 50000
#define EE 500000

// ---------------- scratch (static device globals; no runtime allocation) ----------------
__device__ __align__(16) __half g_xh[(size_t)NN * 128];          // dense fp16 copy of x
__device__ __align__(16) __half g_AbfA[(size_t)NN * 1024];       // ping A' (4 relation means)
__device__ __align__(16) __half g_AbfB[(size_t)NN * 1024];       // pong A'
__device__ __align__(16) __half g_hh[(size_t)NN * 256];          // dense fp16-hi mirror of h
__device__ __align__(16) __half g_Bbf[3][(size_t)256 * 2560];    // main B' slots = [Bhi(5D)|Blo(5D)]
__device__ __align__(16) __half g_Bt[3][(size_t)128 * 512];      // tail B' slots = [Whi|Wlo]
__device__ __align__(16) float g_bf[64];                         // fused clf bias
__device__ __align__(16) float g_bias[3][256];
__device__ __align__(16) float g_h[(size_t)NN * 256];
__device__ __align__(16) float g_h2[(size_t)NN * 256];
__device__ __align__(16) float g_stats[128];
// CSR
__device__ int g_off[4 * (NN + 1)];
__device__ int g_list[4 * EE];
__device__ int g_cur[4 * NN];

// ---------------- helpers ----------------
__device__ __forceinline__ uint32_t smem_u32(const void* p) {
    uint32_t a;
    asm("{ .reg .u64 t; cvta.to.shared.u64 t, %1; cvt.u32.u64 %0, t; }" : "=r"(a) : "l"(p));
    return a;
}
__device__ __forceinline__ void cp_async16(uint32_t dst, const void* src, int sz) {
    asm volatile("cp.async.cg.shared.global [%0], [%1], 16, %2;"
                 :: "r"(dst), "l"(src), "r"(sz) : "memory");
}
__device__ __forceinline__ void cp_commit() { asm volatile("cp.async.commit_group;" ::: "memory"); }
template <int Nw>
__device__ __forceinline__ void cp_wait() { asm volatile("cp.async.wait_group %0;" ::"n"(Nw) : "memory"); }

__device__ __forceinline__ uint32_t pack_h2(__half a, __half b) {
    __half2 t = __halves2half2(a, b);
    return *(uint32_t*)&t;
}
__device__ __forceinline__ uint32_t hi_pack(float x, float y) {
    return pack_h2(__float2half_rn(x), __float2half_rn(y));
}
__device__ __forceinline__ void ldsm4(uint32_t& r0, uint32_t& r1, uint32_t& r2, uint32_t& r3,
                                      uint32_t addr) {
    asm volatile("ldmatrix.sync.aligned.m8n8.x4.shared.b16 {%0,%1,%2,%3}, [%4];"
                 : "=r"(r0), "=r"(r1), "=r"(r2), "=r"(r3) : "r"(addr));
}

// ---------------- CSR build ----------------
__global__ void zero_int(int* __restrict__ p, int n) {
    int i = blockIdx.x * blockDim.x + threadIdx.x;
    if (i < n) p[i] = 0;
}
__global__ void hist_k(const int* __restrict__ e0, const int* __restrict__ e1,
                       const int* __restrict__ e2, const int* __restrict__ e3) {
    int t = blockIdx.y;
    const int* e = (t == 0) ? e0 : (t == 1) ? e1 : (t == 2) ? e2 : e3;
    int i = blockIdx.x * blockDim.x + threadIdx.x;
    if (i < EE) atomicAdd(&g_cur[t * NN + e[EE + i]], 1);
}
__global__ void __launch_bounds__(1024) scan_k() {
    int t = blockIdx.x;
    const int C = (NN + 1023) / 1024;
    __shared__ int wsum[32];
    int start = threadIdx.x * C;
    int s = 0;
    for (int i = 0; i < C; i++) {
        int j = start + i;
        if (j < NN) s += g_cur[t * NN + j];
    }
    int lane = threadIdx.x & 31, w = threadIdx.x >> 5;
    int inc = s;
#pragma unroll
    for (int o = 1; o < 32; o <<= 1) {
        int v = __shfl_up_sync(0xffffffffu, inc, o);
        if (lane >= o) inc += v;
    }
    if (lane == 31) wsum[w] = inc;
    __syncthreads();
    if (w == 0) {
        int ws = wsum[lane];
        int winc = ws;
#pragma unroll
        for (int o = 1; o < 32; o <<= 1) {
            int v = __shfl_up_sync(0xffffffffu, winc, o);
            if (lane >= o) winc += v;
        }
        wsum[lane] = winc - ws;  // exclusive warp offsets
    }
    __syncthreads();
    int a = inc - s + wsum[w];  // exclusive prefix for this thread's chunk
    for (int i = 0; i < C; i++) {
        int j = start + i;
        if (j < NN) {
            int c = g_cur[t * NN + j];
            g_off[t * (NN + 1) + j] = a;
            g_cur[t * NN + j] = a;
            a += c;
        }
    }
    if (threadIdx.x == 0) g_off[t * (NN + 1) + NN] = EE;
}
__global__ void fill_k(const int* __restrict__ e0, const int* __restrict__ e1,
                       const int* __restrict__ e2, const int* __restrict__ e3) {
    int t = blockIdx.y;
    const int* e = (t == 0) ? e0 : (t == 1) ? e1 : (t == 2) ? e2 : e3;
    int i = blockIdx.x * blockDim.x + threadIdx.x;
    if (i < EE) {
        int d = e[EE + i];
        int p = atomicAdd(&g_cur[t * NN + d], 1);
        g_list[t * EE + p] = e[i];
    }
}

// ---------------- one-shot weight preparation ----------------
__device__ void build_main(const float* __restrict__ Wl, const float* __restrict__ Wr,
                           const float* __restrict__ bl, int D, int slot, long i) {
    int k = (int)(i / 256), n = (int)(i % 256);
    float v;
    if (k < 4 * D) {
        v = Wl[(size_t)k * 256 + n];
    } else {
        int kk = k - 4 * D;
        v = Wr[(size_t)kk * 256 + n] + Wr[((size_t)D + kk) * 256 + n] +
            Wr[((size_t)2 * D + kk) * 256 + n] + Wr[((size_t)3 * D + kk) * 256 + n];
    }
    int K2 = 10 * D;
    __half hi = __float2half_rn(v);
    __half lo = __float2half_rn(v - __half2float(hi));
    g_Bbf[slot][(size_t)n * K2 + k] = hi;
    g_Bbf[slot][(size_t)n * K2 + 5 * D + k] = lo;
    if (i < 256) g_bias[slot][i] = bl[i] + bl[256 + i] + bl[512 + i] + bl[768 + i];
}
__device__ void build_tail(const float* __restrict__ W, int K, int Nout, int slot, long i) {
    int n = (int)(i / K), k = (int)(i % K);
    float v = (n < Nout) ? W[(size_t)k * Nout + n] : 0.f;
    __half hi = __float2half_rn(v);
    __half lo = __float2half_rn(v - __half2float(hi));
    g_Bt[slot][(size_t)n * 2 * K + k] = hi;
    g_Bt[slot][(size_t)n * 2 * K + K + k] = lo;
}

__global__ void __launch_bounds__(256) prep_k(
    const float* __restrict__ Wl0, const float* __restrict__ Wr0, const float* __restrict__ bl0,
    const float* __restrict__ Wl, const float* __restrict__ Wr, const float* __restrict__ bl,
    const float* __restrict__ lin_W, const float* __restrict__ pW1,
    const float* __restrict__ pW2, const float* __restrict__ pb2,
    const float* __restrict__ cW1, const float* __restrict__ cb1) {
    int b = blockIdx.x, tid = threadIdx.x;
    if (b < 640) {
        build_main(Wl0, Wr0, bl0, 128, 0, (long)b * 256 + tid);
    } else if (b < 1920) {
        build_main(Wl, Wr, bl, 256, 1, (long)(b - 640) * 256 + tid);
    } else if (b < 3200) {
        build_main(Wl + (size_t)4 * 256 * 256, Wr + (size_t)4 * 256 * 256,
                   bl + (size_t)4 * 256, 256, 2, (long)(b - 1920) * 256 + tid);
    } else if (b < 3328) {
        build_tail(lin_W, 256, 128, 0, (long)(b - 3200) * 256 + tid);
    } else if (b < 3392) {
        build_tail(pW1, 128, 128, 1, (long)(b - 3328) * 256 + tid);
    } else if (b < 3425) {
        long j = (long)(b - 3392) * 256 + tid;
        if (j < 128 * 64) {
            int k = (int)(j >> 6), n = (int)(j & 63);
            float s = 0.f;
            for (int m = 0; m < 128; m++)
                s += pW2[k * 128 + m] * cW1[m * 64 + n];
            __half hi = __float2half_rn(s);
            __half lo = __float2half_rn(s - __half2float(hi));
            g_Bt[2][(size_t)n * 256 + k] = hi;
            g_Bt[2][(size_t)n * 256 + 128 + k] = lo;
        } else if (j < 128 * 64 + 128) {
            int n = 64 + (int)(j - 128 * 64) / 2;
            int half = (int)(j - 128 * 64) & 1;
            for (int k = 0; k < 128; k++)
                g_Bt[2][(size_t)n * 256 + half * 128 + k] = __float2half_rn(0.f);
        }
    } else {
        if (tid < 128) g_stats[tid] = 0.f;
        if (tid >= 128 && tid < 192) {
            int n = tid - 128;
            float s = cb1[n];
            for (int m = 0; m < 128; m++)
                s += pb2[m] * cW1[m * 64 + n];
            g_bf[n] = s;
        }
    }
}

// ---------------- x -> dense fp16 ----------------
__global__ void convert_x(const float* __restrict__ x) {
    long i = (long)blockIdx.x * blockDim.x + threadIdx.x;
    if (i >= (long)NN * 32) return;
    int n = (int)(i >> 5);
    int c = (int)(i & 31) * 4;
    float4 v = *(const float4*)&x[(size_t)n * 128 + c];
    *(uint2*)(g_xh + (size_t)n * 128 + c) = make_uint2(hi_pack(v.x, v.y), hi_pack(v.z, v.w));
}

// ---------------- fp16 CSR gather-aggregate (dst stride 4D), 8-deep MLP ----------------
template <int VP>
__global__ void __launch_bounds__(256) aggregate_h(const __half* __restrict__ src,
                                                   __half* __restrict__ dst) {
    const int D = 32 * VP, KA = 4 * D;
    int wid = threadIdx.x >> 5, lane = threadIdx.x & 31;
    int n = blockIdx.x * 8 + wid;
    int t = blockIdx.y;
    if (n >= NN) return;
    int beg = g_off[t * (NN + 1) + n], end = g_off[t * (NN + 1) + n + 1];
    float acc[VP];
#pragma unroll
    for (int i = 0; i < VP; i++) acc[i] = 0.f;
    const int* lst = g_list + (size_t)t * EE;
    auto addv8 = [&](uint4 v) {
        float2 f0 = __half22float2(*(__half2*)&v.x);
        float2 f1 = __half22float2(*(__half2*)&v.y);
        float2 f2 = __half22float2(*(__half2*)&v.z);
        float2 f3 = __half22float2(*(__half2*)&v.w);
        acc[0] += f0.x; acc[1] += f0.y; acc[2] += f1.x; acc[3] += f1.y;
        acc[4 % VP] += f2.x; acc[5 % VP] += f2.y; acc[6 % VP] += f3.x; acc[7 % VP] += f3.y;
    };
    auto addv4 = [&](uint2 v) {
        float2 f0 = __half22float2(*(__half2*)&v.x);
        float2 f1 = __half22float2(*(__half2*)&v.y);
        acc[0] += f0.x; acc[1] += f0.y; acc[2 % VP] += f1.x; acc[3 % VP] += f1.y;
    };
    int e = beg;
    // 8-deep batches: prefetch 8 indices, issue 8 independent row loads, then reduce
    for (; e + 8 <= end; e += 8) {
        int si[8];
#pragma unroll
        for (int u = 0; u < 8; u++) si[u] = __ldg(&lst[e + u]);
        if (VP == 8) {
            uint4 rv[8];
#pragma unroll
            for (int u = 0; u < 8; u++)
                rv[u] = __ldg((const uint4*)(src + (size_t)si[u] * D + lane * 8));
#pragma unroll
            for (int u = 0; u < 8; u++) addv8(rv[u]);
        } else {
            uint2 rv[8];
#pragma unroll
            for (int u = 0; u < 8; u++)
                rv[u] = __ldg((const uint2*)(src + (size_t)si[u] * D + lane * 4));
#pragma unroll
            for (int u = 0; u < 8; u++) addv4(rv[u]);
        }
    }
    for (; e < end; e++) {
        int s = __ldg(&lst[e]);
        if (VP == 8) addv8(__ldg((const uint4*)(src + (size_t)s * D + lane * 8)));
        else addv4(__ldg((const uint2*)(src + (size_t)s * D + lane * 4)));
    }
    float inv = 1.0f / fmaxf((float)(end - beg), 1.0f);
    uint32_t hw[VP / 2];
#pragma unroll
    for (int i = 0; i < VP / 2; i++) hw[i] = hi_pack(acc[2 * i] * inv, acc[2 * i + 1] * inv);
    __half* d = dst + (size_t)n * KA + t * D + lane * VP;
    if (VP == 8) *(uint4*)d = make_uint4(hw[0], hw[1], hw[2 % (VP / 2)], hw[3 % (VP / 2)]);
    else *(uint2*)d = make_uint2(hw[0], hw[1]);
}

// ---------------- main GNN GEMM: CTA 128x256, warp 64x64, self cols read from mirror ----------------
#define MST 4
#define ASZ 10240
#define BSZ 20480
#define STB 51200
__global__ void __launch_bounds__(256, 1)
mma_main(const __half* __restrict__ A, int strideA,
         const __half* __restrict__ S, int strideS,
         const __half* __restrict__ Bw,
         const float* __restrict__ bias,
         __half* __restrict__ C, int NCb) {
    extern __shared__ char smem[];
    const uint32_t sb = smem_u32(smem);
    const int NCA = (NCb / 5) * 4;
    const int KA5 = NCb * 32;
    const int K2 = 2 * KA5;
    int tid = threadIdx.x;
    int wid = tid >> 5, lane = tid & 31;
    int t4 = lane >> 2, tq = lane & 3;
    int m0 = (wid & 1) * 64, n0 = (wid >> 1) * 64;
    int rowBase = blockIdx.x * 128;

    float acc[4][8][4];
#pragma unroll
    for (int i = 0; i < 4; i++)
#pragma unroll
        for (int j = 0; j < 8; j++)
#pragma unroll
            for (int q = 0; q < 4; q++) acc[i][j][q] = 0.f;

    auto issue = [&](int j, int s) {
        uint32_t abase = sb + s * STB;
        const __half* src;
        int st, col;
        if (j < NCA) { src = A; st = strideA; col = j * 32; }
        else { src = S; st = strideS; col = (j - NCA) * 32; }
#pragma unroll
        for (int i = 0; i < 2; i++) {
            int u = tid + i * 256;
            int r = u >> 2, q = u & 3;
            int gr = rowBase + r;
            cp_async16(abase + r * 80 + q * 16,
                       src + (size_t)gr * st + col + q * 8, gr < NN ? 16 : 0);
        }
#pragma unroll
        for (int p = 0; p < 2; p++) {
            uint32_t bb = abase + ASZ + p * BSZ;
#pragma unroll
            for (int i = 0; i < 4; i++) {
                int u = tid + i * 256;
                int r = u >> 2, q = u & 3;
                cp_async16(bb + r * 80 + q * 16,
                           Bw + (size_t)r * K2 + p * KA5 + j * 32 + q * 8, 16);
            }
        }
        cp_commit();
    };

    uint32_t aOff = (uint32_t)((m0 + (lane & 15)) * 80 + (lane >> 4) * 16);
    uint32_t bOff = (uint32_t)((n0 + ((lane >> 4) << 3) + (lane & 7)) * 80 + ((lane >> 3) & 1) * 16);

    issue(0, 0);
    issue(1, 1);
    issue(2, 2);

    for (int j = 0; j < NCb; j++) {
        int s = j & (MST - 1);
        int younger = NCb - 1 - j;
        if (younger >= 2) cp_wait<2>();
        else if (younger == 1) cp_wait<1>();
        else cp_wait<0>();
        __syncthreads();
        uint32_t abase = sb + s * STB;
#pragma unroll
        for (int ks = 0; ks < 2; ks++) {
            uint32_t a[4][4];
#pragma unroll
            for (int tm = 0; tm < 4; tm++)
                ldsm4(a[tm][0], a[tm][1], a[tm][2], a[tm][3],
                      abase + aOff + tm * 1280 + ks * 32);
#pragma unroll
            for (int p = 0; p < 2; p++) {
                uint32_t bbase = abase + ASZ + p * BSZ;
                uint32_t b[4][4];
#pragma unroll
                for (int tb = 0; tb < 4; tb++)
                    ldsm4(b[tb][0], b[tb][1], b[tb][2], b[tb][3],
                          bbase + bOff + tb * 1280 + ks * 32);
#pragma unroll
                for (int tm = 0; tm < 4; tm++)
#pragma unroll
                    for (int tn = 0; tn < 8; tn++) {
                        uint32_t b0 = b[tn >> 1][(tn & 1) * 2];
                        uint32_t b1 = b[tn >> 1][(tn & 1) * 2 + 1];
                        asm volatile(
                            "mma.sync.aligned.m16n8k16.row.col.f32.f16.f16.f32 "
                            "{%0,%1,%2,%3}, {%4,%5,%6,%7}, {%8,%9}, {%0,%1,%2,%3};"
                            : "+f"(acc[tm][tn][0]), "+f"(acc[tm][tn][1]),
                              "+f"(acc[tm][tn][2]), "+f"(acc[tm][tn][3])
                            : "r"(a[tm][0]), "r"(a[tm][1]), "r"(a[tm][2]), "r"(a[tm][3]),
                              "r"(b0), "r"(b1));
                    }
            }
        }
        __syncthreads();
        if (j + 3 < NCb) issue(j + 3, (j + 3) & (MST - 1));
    }

#pragma unroll
    for (int tm = 0; tm < 4; tm++) {
        int r0 = rowBase + m0 + tm * 16 + t4;
        int r1 = r0 + 8;
#pragma unroll
        for (int tn = 0; tn < 8; tn++) {
            int col = n0 + tn * 8 + tq * 2;
            float bx = bias[col], by = bias[col + 1];
            if (r0 < NN)
                *(uint32_t*)(C + (size_t)r0 * 256 + col) =
                    hi_pack(fmaxf(acc[tm][tn][0] + bx, 0.f), fmaxf(acc[tm][tn][1] + by, 0.f));
            if (r1 < NN)
                *(uint32_t*)(C + (size_t)r1 * 256 + col) =
                    hi_pack(fmaxf(acc[tm][tn][2] + bx, 0.f), fmaxf(acc[tm][tn][3] + by, 0.f));
        }
    }
}

// ---------------- generic tail fp16 GEMM (CTA 128x128, warp 32x64) ----------------
__global__ void __launch_bounds__(256, 2)
mma_gemm(const __half* __restrict__ A, int KA,
         const __half* __restrict__ B, int K3,
         const float* __restrict__ bias, float* __restrict__ Cf,
         int ldc, int Nout, int relu,
         __half* __restrict__ Chl, int hlStride) {
    __shared__ __half As[2][128][40];
    __shared__ __half Bs[2][128][40];
    int tid = threadIdx.x;
    int wid = tid >> 5, lane = tid & 31;
    int t4 = lane >> 2, tq = lane & 3;
    int warp_m = wid & 3;
    int warp_n = wid >> 2;
    int rowBase = blockIdx.y * 128;
    int m0 = warp_m * 32, n0 = warp_n * 64;
    int NCb = KA / 32;
    int NC = 2 * NCb;

    float acc[2][8][4];
#pragma unroll
    for (int i = 0; i < 2; i++)
#pragma unroll
        for (int j = 0; j < 8; j++)
#pragma unroll
            for (int q = 0; q < 4; q++) acc[i][j][q] = 0.f;

    auto issue = [&](int cc, int s) {
        int ac = (cc < NCb) ? cc : cc - NCb;
#pragma unroll
        for (int i = 0; i < 2; i++) {
            int u = tid + i * 256;
            int r = u >> 2, q = u & 3;
            int gr = rowBase + r;
            cp_async16(smem_u32(&As[s][r][q * 8]),
                       A + (size_t)gr * KA + ac * 32 + q * 8, gr < NN ? 16 : 0);
            cp_async16(smem_u32(&Bs[s][r][q * 8]),
                       B + (size_t)r * K3 + cc * 32 + q * 8, 16);
        }
        cp_commit();
    };

    issue(0, 0);

    for (int c = 0; c < NC; c++) {
        int s = c & 1;
        if (c + 1 < NC) {
            issue(c + 1, s ^ 1);
            cp_wait<1>();
        } else {
            cp_wait<0>();
        }
        __syncthreads();
        const __half(*as)[40] = As[s];
        const __half(*bs)[40] = Bs[s];
#pragma unroll
        for (int ks = 0; ks < 2; ks++) {
            uint32_t a[2][4], b[8][2];
#pragma unroll
            for (int im = 0; im < 2; im++) {
                int rm = m0 + im * 16 + t4;
                int kc = ks * 16 + tq * 2;
                a[im][0] = *(const uint32_t*)&as[rm][kc];
                a[im][1] = *(const uint32_t*)&as[rm + 8][kc];
                a[im][2] = *(const uint32_t*)&as[rm][kc + 8];
                a[im][3] = *(const uint32_t*)&as[rm + 8][kc + 8];
            }
#pragma unroll
            for (int in = 0; in < 8; in++) {
                int rn = n0 + in * 8 + t4;
                int kc = ks * 16 + tq * 2;
                b[in][0] = *(const uint32_t*)&bs[rn][kc];
                b[in][1] = *(const uint32_t*)&bs[rn][kc + 8];
            }
#pragma unroll
            for (int im = 0; im < 2; im++)
#pragma unroll
                for (int in = 0; in < 8; in++) {
                    asm volatile(
                        "mma.sync.aligned.m16n8k16.row.col.f32.f16.f16.f32 "
                        "{%0,%1,%2,%3}, {%4,%5,%6,%7}, {%8,%9}, {%0,%1,%2,%3};"
                        : "+f"(acc[im][in][0]), "+f"(acc[im][in][1]),
                          "+f"(acc[im][in][2]), "+f"(acc[im][in][3])
                        : "r"(a[im][0]), "r"(a[im][1]), "r"(a[im][2]), "r"(a[im][3]),
                          "r"(b[in][0]), "r"(b[in][1]));
                }
        }
        __syncthreads();
    }

#pragma unroll
    for (int im = 0; im < 2; im++) {
        int gr0 = rowBase + m0 + im * 16 + t4;
#pragma unroll
        for (int in = 0; in < 8; in++) {
            int col = n0 + in * 8 + tq * 2;
            if (col >= Nout) continue;
            float bx = bias[col], by = bias[col + 1];
            float v0x = acc[im][in][0] + bx, v0y = acc[im][in][1] + by;
            float v1x = acc[im][in][2] + bx, v1y = acc[im][in][3] + by;
            if (relu) {
                v0x = fmaxf(v0x, 0.f); v0y = fmaxf(v0y, 0.f);
                v1x = fmaxf(v1x, 0.f); v1y = fmaxf(v1y, 0.f);
            }
            if (gr0 < NN) {
                if (Cf) *(float2*)&Cf[(size_t)gr0 * ldc + col] = make_float2(v0x, v0y);
                if (Chl) *(uint32_t*)(Chl + (size_t)gr0 * hlStride + col) = hi_pack(v0x, v0y);
            }
            if (gr0 + 8 < NN) {
                if (Cf) *(float2*)&Cf[(size_t)(gr0 + 8) * ldc + col] = make_float2(v1x, v1y);
                if (Chl) *(uint32_t*)(Chl + (size_t)(gr0 + 8) * hlStride + col) = hi_pack(v1x, v1y);
            }
        }
    }
}

// ---------------- tail kernels ----------------
// fused onset-pool (relation 0) + LayerNorm, fp16 in -> fp16 hi out, stride 128
__global__ void __launch_bounds__(256) pool_ln(const __half* __restrict__ hin,
                                               __half* __restrict__ dst,
                                               const float* __restrict__ g,
                                               const float* __restrict__ b) {
    int wid = threadIdx.x >> 5, lane = threadIdx.x & 31;
    int n = blockIdx.x * 8 + wid;
    if (n >= NN) return;
    int beg = g_off[n], end = g_off[n + 1];
    float acc[4];
    {
        uint2 v = __ldg((const uint2*)(hin + (size_t)n * 128 + lane * 4));
        float2 f0 = __half22float2(*(__half2*)&v.x);
        float2 f1 = __half22float2(*(__half2*)&v.y);
        acc[0] = f0.x; acc[1] = f0.y; acc[2] = f1.x; acc[3] = f1.y;
    }
    auto addv = [&](uint2 v) {
        float2 f0 = __half22float2(*(__half2*)&v.x);
        float2 f1 = __half22float2(*(__half2*)&v.y);
        acc[0] += f0.x; acc[1] += f0.y; acc[2] += f1.x; acc[3] += f1.y;
    };
    int e = beg;
    for (; e + 4 <= end; e += 4) {
        int si[4];
#pragma unroll
        for (int u = 0; u < 4; u++) si[u] = __ldg(&g_list[e + u]);
        uint2 rv[4];
#pragma unroll
        for (int u = 0; u < 4; u++)
            rv[u] = __ldg((const uint2*)(hin + (size_t)si[u] * 128 + lane * 4));
#pragma unroll
        for (int u = 0; u < 4; u++) addv(rv[u]);
    }
    for (; e < end; e++) addv(__ldg((const uint2*)(hin + (size_t)__ldg(&g_list[e]) * 128 + lane * 4)));
    float inv = 1.0f / fmaxf((float)(end - beg), 1.0f);
#pragma unroll
    for (int i = 0; i < 4; i++) acc[i] *= inv;
    float s = acc[0] + acc[1] + acc[2] + acc[3];
    float q = acc[0] * acc[0] + acc[1] * acc[1] + acc[2] * acc[2] + acc[3] * acc[3];
#pragma unroll
    for (int o = 16; o; o >>= 1) {
        s += __shfl_xor_sync(0xffffffffu, s, o);
        q += __shfl_xor_sync(0xffffffffu, q, o);
    }
    float mu = s * (1.0f / 128.0f);
    float var = q * (1.0f / 128.0f) - mu * mu;
    float r = rsqrtf(var + 1e-5f);
    float4 gg = *(const float4*)&g[lane * 4];
    float4 bb = *(const float4*)&b[lane * 4];
    float ox = (acc[0] - mu) * r * gg.x + bb.x;
    float oy = (acc[1] - mu) * r * gg.y + bb.y;
    float oz = (acc[2] - mu) * r * gg.z + bb.z;
    float ow = (acc[3] - mu) * r * gg.w + bb.w;
    *(uint2*)(dst + (size_t)n * 128 + lane * 4) =
        make_uint2(hi_pack(ox, oy), hi_pack(oz, ow));
}

// LayerNorm (dim 128) fp32 in -> fp16 hi out, stride 128
__global__ void layernorm_hl(const float* __restrict__ in, __half* __restrict__ dst,
                             const float* __restrict__ g, const float* __restrict__ b) {
    int row = blockIdx.x * 8 + (threadIdx.x >> 5);
    int lane = threadIdx.x & 31;
    if (row >= NN) return;
    float4 v = *(const float4*)&in[(size_t)row * 128 + lane * 4];
    float s = v.x + v.y + v.z + v.w;
    float q = v.x * v.x + v.y * v.y + v.z * v.z + v.w * v.w;
#pragma unroll
    for (int o = 16; o; o >>= 1) {
        s += __shfl_xor_sync(0xffffffffu, s, o);
        q += __shfl_xor_sync(0xffffffffu, q, o);
    }
    float mu = s * (1.0f / 128.0f);
    float var = q * (1.0f / 128.0f) - mu * mu;
    float r = rsqrtf(var + 1e-5f);
    float4 gg = *(const float4*)&g[lane * 4];
    float4 bb = *(const float4*)&b[lane * 4];
    float ox = (v.x - mu) * r * gg.x + bb.x;
    float oy = (v.y - mu) * r * gg.y + bb.y;
    float oz = (v.z - mu) * r * gg.z + bb.z;
    float ow = (v.w - mu) * r * gg.w + bb.w;
    *(uint2*)(dst + (size_t)row * 128 + lane * 4) =
        make_uint2(hi_pack(ox, oy), hi_pack(oz, ow));
}

__global__ void bn_stats(const float* __restrict__ z) {
    __shared__ float ssum[256], ssq[256];
    int c = threadIdx.x & 63;
    int sub = threadIdx.x >> 6;
    float s = 0.f, q = 0.f;
    for (long r = (long)blockIdx.x * 4 + sub; r < NN; r += (long)gridDim.x * 4) {
        float v = z[r * 64 + c];
        s += v; q += v * v;
    }
    ssum[threadIdx.x] = s; ssq[threadIdx.x] = q;
    __syncthreads();
    if (sub == 0) {
        s = ssum[c] + ssum[64 + c] + ssum[128 + c] + ssum[192 + c];
        q = ssq[c] + ssq[64 + c] + ssq[128 + c] + ssq[192 + c];
        atomicAdd(&g_stats[c], s);
        atomicAdd(&g_stats[64 + c], q);
    }
}

__global__ void finalize_k(const float* __restrict__ z, const float* __restrict__ bn_g,
                           const float* __restrict__ bn_b, const float* __restrict__ cW2,
                           const float* __restrict__ cb2, float* __restrict__ out) {
    __shared__ float w[448], smu[64], sr[64], sg[64], sb[64], sb2[7];
    int tid = threadIdx.x;
    for (int i = tid; i < 448; i += blockDim.x) w[i] = cW2[i];
    if (tid < 64) {
        float mu = g_stats[tid] / (float)NN;
        float var = g_stats[64 + tid] / (float)NN - mu * mu;
        smu[tid] = mu;
        sr[tid] = rsqrtf(var + 1e-5f);
        sg[tid] = bn_g[tid];
        sb[tid] = bn_b[tid];
    }
    if (tid < 7) sb2[tid] = cb2[tid];
    __syncthreads();
    int row = blockIdx.x * blockDim.x + tid;
    if (row >= NN) return;
    float logits[7];
#pragma unroll
    for (int j = 0; j < 7; j++) logits[j] = sb2[j];
    for (int c = 0; c < 64; c += 4) {
        float4 v4 = *(const float4*)&z[(size_t)row * 64 + c];
        float vv[4] = {v4.x, v4.y, v4.z, v4.w};
#pragma unroll
        for (int u = 0; u < 4; u++) {
            int cc = c + u;
            float v = (vv[u] - smu[cc]) * sr[cc] * sg[cc] + sb[cc];
#pragma unroll
            for (int j = 0; j < 7; j++) logits[j] += v * w[cc * 7 + j];
        }
    }
    float m = logits[0];
#pragma unroll
    for (int j = 1; j < 7; j++) m = fmaxf(m, logits[j]);
    float ssum = 0.f;
#pragma unroll
    for (int j = 0; j < 7; j++) { logits[j] = expf(logits[j] - m); ssum += logits[j]; }
    float inv = 1.0f / ssum;
#pragma unroll
    for (int j = 0; j < 7; j++) out[(size_t)row * 7 + j] = logits[j] * inv;
}

// ---------------- host launcher ----------------
static inline int cdiv(long a, int b) { return (int)((a + b - 1) / b); }

extern "C" void kernel_launch(void* const* d_in, const int* in_sizes, int n_in,
                              void* d_out, int out_size) {
    const float* x = (const float*)d_in[0];
    const int* e0 = (const int*)d_in[1];
    const int* e1 = (const int*)d_in[2];
    const int* e2 = (const int*)d_in[3];
    const int* e3 = (const int*)d_in[4];
    const float* Wl0 = (const float*)d_in[5];
    const float* bl0 = (const float*)d_in[6];
    const float* Wr0 = (const float*)d_in[7];
    const float* Wl = (const float*)d_in[8];
    const float* bl = (const float*)d_in[9];
    const float* Wr = (const float*)d_in[10];
    const float* lin_W = (const float*)d_in[11];
    const float* lin_b = (const float*)d_in[12];
    const float* norm_g = (const float*)d_in[13];
    const float* norm_b = (const float*)d_in[14];
    const float* pW1 = (const float*)d_in[15];
    const float* pb1 = (const float*)d_in[16];
    const float* pln_g = (const float*)d_in[17];
    const float* pln_b = (const float*)d_in[18];
    const float* pW2 = (const float*)d_in[19];
    const float* pb2 = (const float*)d_in[20];
    const float* cW1 = (const float*)d_in[21];
    const float* cb1 = (const float*)d_in[22];
    const float* bn_g = (const float*)d_in[23];
    const float* bn_b = (const float*)d_in[24];
    const float* cW2 = (const float*)d_in[25];
    const float* cb2 = (const float*)d_in[26];
    float* out = (float*)d_out;

    float *ph, *ph2, *pbf;
    __half *pA, *pB, *phh, *pxh;
    __half (*pBbf)[(size_t)256 * 2560];
    __half (*pBt)[(size_t)128 * 512];
    float (*pbias)[256];
    int* pcur;
    cudaGetSymbolAddress((void**)&pA, g_AbfA);
    cudaGetSymbolAddress((void**)&pB, g_AbfB);
    cudaGetSymbolAddress((void**)&phh, g_hh);
    cudaGetSymbolAddress((void**)&pxh, g_xh);
    cudaGetSymbolAddress((void**)&pBbf, g_Bbf);
    cudaGetSymbolAddress((void**)&pBt, g_Bt);
    cudaGetSymbolAddress((void**)&pbf, g_bf);
    cudaGetSymbolAddress((void**)&pbias, g_bias);
    cudaGetSymbolAddress((void**)&ph, g_h);
    cudaGetSymbolAddress((void**)&ph2, g_h2);
    cudaGetSymbolAddress((void**)&pcur, g_cur);

    static bool attr_set = false;
    if (!attr_set) {
        cudaFuncSetAttribute(mma_main, cudaFuncAttributeMaxDynamicSharedMemorySize, MST * STB);
        attr_set = true;
    }

    const int T = 256;
    const int RB = cdiv(NN, 128);
    const dim3 TAIL_GRID(1, RB);
    const dim3 AGG_GRID(cdiv(NN, 8), 4);
    const dim3 EDGE_GRID(cdiv(EE, T), 4);

    // ---- CSR build + all weight prep ----
    zero_int<<<cdiv(4L * NN, T), T>>>(pcur, 4 * NN);
    hist_k<<<EDGE_GRID, T>>>(e0, e1, e2, e3);
    scan_k<<<4, 1024>>>();
    fill_k<<<EDGE_GRID, T>>>(e0, e1, e2, e3);
    prep_k<<<3426, 256>>>(Wl0, Wr0, bl0, Wl, Wr, bl, lin_W, pW1, pW2, pb2, cW1, cb1);
    convert_x<<<cdiv((long)NN * 32, T), T>>>(x);

    // ---- Layer 0 (D=128) ----
    aggregate_h<4><<<AGG_GRID, 256>>>(pxh, pA);
    mma_main<<<RB, 256, MST * STB>>>(pA, 512, pxh, 128, pBbf[0], pbias[0], phh, 20);

    // ---- Layer 1 (D=256) ----
    aggregate_h<8><<<AGG_GRID, 256>>>(phh, pB);
    mma_main<<<RB, 256, MST * STB>>>(pB, 1024, phh, 256, pBbf[1], pbias[1], phh, 40);

    // ---- Layer 2 ----
    aggregate_h<8><<<AGG_GRID, 256>>>(phh, pA);
    mma_main<<<RB, 256, MST * STB>>>(pA, 1024, phh, 256, pBbf[2], pbias[2], phh, 40);

    // ---- lin -> fp16 hi (pA, stride 128) ----
    mma_gemm<<<TAIL_GRID, 256>>>(phh, 256, pBt[0], 512, lin_b, nullptr, 128, 128, 0, pA, 128);

    // fused onset pooling + LN1 -> hi (pB, stride 128)
    pool_ln<<<cdiv(NN, 8), 256>>>(pA, pB, norm_g, norm_b);

    // pW1 (relu) -> fp32 g_h2
    mma_gemm<<<TAIL_GRID, 256>>>(pB, 128, pBt[1], 256, pb1, ph2, 128, 128, 1, nullptr, 0);
    // LN2 -> hi (pA, stride 128)
    layernorm_hl<<<cdiv(NN, 8), 256>>>(ph2, pA, pln_g, pln_b);
    // fused (pW2@cW1) GEMM: relu(h @ W' + b') -> fp32 g_h (ldc 64)
    mma_gemm<<<TAIL_GRID, 256>>>(pA, 128, pBt[2], 256, pbf, ph, 64, 64, 1, nullptr, 0);

    bn_stats<<<512, 256>>>(ph);
    finalize_k<<<cdiv(NN, 256), 256>>>(ph, bn_g, bn_b, cW2, cb2, out);
}

// round 17
// speedup vs baseline: 1.0095x; 1.0095x over previous
#include <cuda_runtime.h>
#include <cuda_fp16.h>
#include <cstdint>

#define NN 50000
#define EE 500000

// ---------------- scratch (static device globals; no runtime allocation) ----------------
__device__ __align__(16) __half g_xh[(size_t)NN * 128];          // dense fp16 copy of x
__device__ __align__(16) __half g_AbfA[(size_t)NN * 1024];       // ping A' (4 relation means)
__device__ __align__(16) __half g_AbfB[(size_t)NN * 1024];       // pong A'
__device__ __align__(16) __half g_hh[(size_t)NN * 256];          // dense fp16-hi mirror of h
__device__ __align__(16) __half g_Bbf[3][(size_t)256 * 2560];    // main B' slots = [Bhi(5D)|Blo(5D)]
__device__ __align__(16) __half g_Bt[3][(size_t)128 * 512];      // tail B' slots = [Whi|Wlo]
__device__ __align__(16) float g_bf[64];                         // fused clf bias
__device__ __align__(16) float g_bias[3][256];
__device__ __align__(16) float g_h[(size_t)NN * 256];
__device__ __align__(16) float g_h2[(size_t)NN * 256];
__device__ __align__(16) float g_stats[128];
// CSR
__device__ int g_off[4 * (NN + 1)];
__device__ int g_list[4 * EE];
__device__ int g_cur[4 * NN];

// ---------------- helpers ----------------
__device__ __forceinline__ uint32_t smem_u32(const void* p) {
    uint32_t a;
    asm("{ .reg .u64 t; cvta.to.shared.u64 t, %1; cvt.u32.u64 %0, t; }" : "=r"(a) : "l"(p));
    return a;
}
__device__ __forceinline__ void cp_async16(uint32_t dst, const void* src, int sz) {
    asm volatile("cp.async.cg.shared.global [%0], [%1], 16, %2;"
                 :: "r"(dst), "l"(src), "r"(sz) : "memory");
}
__device__ __forceinline__ void cp_commit() { asm volatile("cp.async.commit_group;" ::: "memory"); }
template <int Nw>
__device__ __forceinline__ void cp_wait() { asm volatile("cp.async.wait_group %0;" ::"n"(Nw) : "memory"); }

__device__ __forceinline__ uint32_t pack_h2(__half a, __half b) {
    __half2 t = __halves2half2(a, b);
    return *(uint32_t*)&t;
}
__device__ __forceinline__ uint32_t hi_pack(float x, float y) {
    return pack_h2(__float2half_rn(x), __float2half_rn(y));
}
__device__ __forceinline__ void ldsm4(uint32_t& r0, uint32_t& r1, uint32_t& r2, uint32_t& r3,
                                      uint32_t addr) {
    asm volatile("ldmatrix.sync.aligned.m8n8.x4.shared.b16 {%0,%1,%2,%3}, [%4];"
                 : "=r"(r0), "=r"(r1), "=r"(r2), "=r"(r3) : "r"(addr));
}

// ---------------- CSR build ----------------
__global__ void zero_int(int* __restrict__ p, int n) {
    int i = blockIdx.x * blockDim.x + threadIdx.x;
    if (i < n) p[i] = 0;
}
// 4 edges/thread, int4 dst loads
__global__ void hist_k(const int* __restrict__ e0, const int* __restrict__ e1,
                       const int* __restrict__ e2, const int* __restrict__ e3) {
    int t = blockIdx.y;
    const int* e = (t == 0) ? e0 : (t == 1) ? e1 : (t == 2) ? e2 : e3;
    int i = (blockIdx.x * blockDim.x + threadIdx.x) * 4;
    if (i >= EE) return;
    int4 d = *(const int4*)(e + EE + i);
    atomicAdd(&g_cur[t * NN + d.x], 1);
    atomicAdd(&g_cur[t * NN + d.y], 1);
    atomicAdd(&g_cur[t * NN + d.z], 1);
    atomicAdd(&g_cur[t * NN + d.w], 1);
}
__global__ void __launch_bounds__(1024) scan_k() {
    int t = blockIdx.x;
    const int C = (NN + 1023) / 1024;
    __shared__ int wsum[32];
    int start = threadIdx.x * C;
    int s = 0;
    for (int i = 0; i < C; i++) {
        int j = start + i;
        if (j < NN) s += g_cur[t * NN + j];
    }
    int lane = threadIdx.x & 31, w = threadIdx.x >> 5;
    int inc = s;
#pragma unroll
    for (int o = 1; o < 32; o <<= 1) {
        int v = __shfl_up_sync(0xffffffffu, inc, o);
        if (lane >= o) inc += v;
    }
    if (lane == 31) wsum[w] = inc;
    __syncthreads();
    if (w == 0) {
        int ws = wsum[lane];
        int winc = ws;
#pragma unroll
        for (int o = 1; o < 32; o <<= 1) {
            int v = __shfl_up_sync(0xffffffffu, winc, o);
            if (lane >= o) winc += v;
        }
        wsum[lane] = winc - ws;  // exclusive warp offsets
    }
    __syncthreads();
    int a = inc - s + wsum[w];  // exclusive prefix for this thread's chunk
    for (int i = 0; i < C; i++) {
        int j = start + i;
        if (j < NN) {
            int c = g_cur[t * NN + j];
            g_off[t * (NN + 1) + j] = a;
            g_cur[t * NN + j] = a;
            a += c;
        }
    }
    if (threadIdx.x == 0) g_off[t * (NN + 1) + NN] = EE;
}
// 4 edges/thread, int4 src+dst loads
__global__ void fill_k(const int* __restrict__ e0, const int* __restrict__ e1,
                       const int* __restrict__ e2, const int* __restrict__ e3) {
    int t = blockIdx.y;
    const int* e = (t == 0) ? e0 : (t == 1) ? e1 : (t == 2) ? e2 : e3;
    int i = (blockIdx.x * blockDim.x + threadIdx.x) * 4;
    if (i >= EE) return;
    int4 srcv = *(const int4*)(e + i);
    int4 d = *(const int4*)(e + EE + i);
    int* lst = g_list + (size_t)t * EE;
    lst[atomicAdd(&g_cur[t * NN + d.x], 1)] = srcv.x;
    lst[atomicAdd(&g_cur[t * NN + d.y], 1)] = srcv.y;
    lst[atomicAdd(&g_cur[t * NN + d.z], 1)] = srcv.z;
    lst[atomicAdd(&g_cur[t * NN + d.w], 1)] = srcv.w;
}

// ---------------- one-shot weight preparation ----------------
__device__ void build_main(const float* __restrict__ Wl, const float* __restrict__ Wr,
                           const float* __restrict__ bl, int D, int slot, long i) {
    int k = (int)(i / 256), n = (int)(i % 256);
    float v;
    if (k < 4 * D) {
        v = Wl[(size_t)k * 256 + n];
    } else {
        int kk = k - 4 * D;
        v = Wr[(size_t)kk * 256 + n] + Wr[((size_t)D + kk) * 256 + n] +
            Wr[((size_t)2 * D + kk) * 256 + n] + Wr[((size_t)3 * D + kk) * 256 + n];
    }
    int K2 = 10 * D;
    __half hi = __float2half_rn(v);
    __half lo = __float2half_rn(v - __half2float(hi));
    g_Bbf[slot][(size_t)n * K2 + k] = hi;
    g_Bbf[slot][(size_t)n * K2 + 5 * D + k] = lo;
    if (i < 256) g_bias[slot][i] = bl[i] + bl[256 + i] + bl[512 + i] + bl[768 + i];
}
__device__ void build_tail(const float* __restrict__ W, int K, int Nout, int slot, long i) {
    int n = (int)(i / K), k = (int)(i % K);
    float v = (n < Nout) ? W[(size_t)k * Nout + n] : 0.f;
    __half hi = __float2half_rn(v);
    __half lo = __float2half_rn(v - __half2float(hi));
    g_Bt[slot][(size_t)n * 2 * K + k] = hi;
    g_Bt[slot][(size_t)n * 2 * K + K + k] = lo;
}

__global__ void __launch_bounds__(256) prep_k(
    const float* __restrict__ Wl0, const float* __restrict__ Wr0, const float* __restrict__ bl0,
    const float* __restrict__ Wl, const float* __restrict__ Wr, const float* __restrict__ bl,
    const float* __restrict__ lin_W, const float* __restrict__ pW1,
    const float* __restrict__ pW2, const float* __restrict__ pb2,
    const float* __restrict__ cW1, const float* __restrict__ cb1) {
    int b = blockIdx.x, tid = threadIdx.x;
    if (b < 640) {
        build_main(Wl0, Wr0, bl0, 128, 0, (long)b * 256 + tid);
    } else if (b < 1920) {
        build_main(Wl, Wr, bl, 256, 1, (long)(b - 640) * 256 + tid);
    } else if (b < 3200) {
        build_main(Wl + (size_t)4 * 256 * 256, Wr + (size_t)4 * 256 * 256,
                   bl + (size_t)4 * 256, 256, 2, (long)(b - 1920) * 256 + tid);
    } else if (b < 3328) {
        build_tail(lin_W, 256, 128, 0, (long)(b - 3200) * 256 + tid);
    } else if (b < 3392) {
        build_tail(pW1, 128, 128, 1, (long)(b - 3328) * 256 + tid);
    } else if (b < 3425) {
        long j = (long)(b - 3392) * 256 + tid;
        if (j < 128 * 64) {
            int k = (int)(j >> 6), n = (int)(j & 63);
            float s = 0.f;
            for (int m = 0; m < 128; m++)
                s += pW2[k * 128 + m] * cW1[m * 64 + n];
            __half hi = __float2half_rn(s);
            __half lo = __float2half_rn(s - __half2float(hi));
            g_Bt[2][(size_t)n * 256 + k] = hi;
            g_Bt[2][(size_t)n * 256 + 128 + k] = lo;
        } else if (j < 128 * 64 + 128) {
            int n = 64 + (int)(j - 128 * 64) / 2;
            int half = (int)(j - 128 * 64) & 1;
            for (int k = 0; k < 128; k++)
                g_Bt[2][(size_t)n * 256 + half * 128 + k] = __float2half_rn(0.f);
        }
    } else {
        if (tid < 128) g_stats[tid] = 0.f;
        if (tid >= 128 && tid < 192) {
            int n = tid - 128;
            float s = cb1[n];
            for (int m = 0; m < 128; m++)
                s += pb2[m] * cW1[m * 64 + n];
            g_bf[n] = s;
        }
    }
}

// ---------------- x -> dense fp16 ----------------
__global__ void convert_x(const float* __restrict__ x) {
    long i = (long)blockIdx.x * blockDim.x + threadIdx.x;
    if (i >= (long)NN * 32) return;
    int n = (int)(i >> 5);
    int c = (int)(i & 31) * 4;
    float4 v = *(const float4*)&x[(size_t)n * 128 + c];
    *(uint2*)(g_xh + (size_t)n * 128 + c) = make_uint2(hi_pack(v.x, v.y), hi_pack(v.z, v.w));
}

// ---------------- fp16 CSR gather-aggregate (dst stride 4D), 4-deep MLP ----------------
template <int VP>
__global__ void __launch_bounds__(256) aggregate_h(const __half* __restrict__ src,
                                                   __half* __restrict__ dst) {
    const int D = 32 * VP, KA = 4 * D;
    int wid = threadIdx.x >> 5, lane = threadIdx.x & 31;
    int n = blockIdx.x * 8 + wid;
    int t = blockIdx.y;
    if (n >= NN) return;
    int beg = g_off[t * (NN + 1) + n], end = g_off[t * (NN + 1) + n + 1];
    float acc[VP];
#pragma unroll
    for (int i = 0; i < VP; i++) acc[i] = 0.f;
    const int* lst = g_list + (size_t)t * EE;
    auto addrow = [&](int s) {
        if (VP == 8) {
            uint4 v = __ldg((const uint4*)(src + (size_t)s * D + lane * 8));
            float2 f0 = __half22float2(*(__half2*)&v.x);
            float2 f1 = __half22float2(*(__half2*)&v.y);
            float2 f2 = __half22float2(*(__half2*)&v.z);
            float2 f3 = __half22float2(*(__half2*)&v.w);
            acc[0] += f0.x; acc[1] += f0.y; acc[2] += f1.x; acc[3] += f1.y;
            acc[4 % VP] += f2.x; acc[5 % VP] += f2.y; acc[6 % VP] += f3.x; acc[7 % VP] += f3.y;
        } else {
            uint2 v = __ldg((const uint2*)(src + (size_t)s * D + lane * 4));
            float2 f0 = __half22float2(*(__half2*)&v.x);
            float2 f1 = __half22float2(*(__half2*)&v.y);
            acc[0] += f0.x; acc[1] += f0.y; acc[2 % VP] += f1.x; acc[3 % VP] += f1.y;
        }
    };
    int e = beg;
    for (; e + 4 <= end; e += 4) {
        int s0 = __ldg(&lst[e]);
        int s1 = __ldg(&lst[e + 1]);
        int s2 = __ldg(&lst[e + 2]);
        int s3 = __ldg(&lst[e + 3]);
        addrow(s0); addrow(s1); addrow(s2); addrow(s3);
    }
    for (; e < end; e++) addrow(__ldg(&lst[e]));
    float inv = 1.0f / fmaxf((float)(end - beg), 1.0f);
    uint32_t hw[VP / 2];
#pragma unroll
    for (int i = 0; i < VP / 2; i++) hw[i] = hi_pack(acc[2 * i] * inv, acc[2 * i + 1] * inv);
    __half* d = dst + (size_t)n * KA + t * D + lane * VP;
    if (VP == 8) *(uint4*)d = make_uint4(hw[0], hw[1], hw[2 % (VP / 2)], hw[3 % (VP / 2)]);
    else *(uint2*)d = make_uint2(hw[0], hw[1]);
}

// ---------------- main GNN GEMM: CTA 128x256, warp 64x64, self cols read from mirror ----------------
#define MST 4
#define ASZ 10240
#define BSZ 20480
#define STB 51200
__global__ void __launch_bounds__(256, 1)
mma_main(const __half* __restrict__ A, int strideA,
         const __half* __restrict__ S, int strideS,
         const __half* __restrict__ Bw,
         const float* __restrict__ bias,
         __half* __restrict__ C, int NCb) {
    extern __shared__ char smem[];
    const uint32_t sb = smem_u32(smem);
    const int NCA = (NCb / 5) * 4;
    const int KA5 = NCb * 32;
    const int K2 = 2 * KA5;
    int tid = threadIdx.x;
    int wid = tid >> 5, lane = tid & 31;
    int t4 = lane >> 2, tq = lane & 3;
    int m0 = (wid & 1) * 64, n0 = (wid >> 1) * 64;
    int rowBase = blockIdx.x * 128;

    float acc[4][8][4];
#pragma unroll
    for (int i = 0; i < 4; i++)
#pragma unroll
        for (int j = 0; j < 8; j++)
#pragma unroll
            for (int q = 0; q < 4; q++) acc[i][j][q] = 0.f;

    auto issue = [&](int j, int s) {
        uint32_t abase = sb + s * STB;
        const __half* src;
        int st, col;
        if (j < NCA) { src = A; st = strideA; col = j * 32; }
        else { src = S; st = strideS; col = (j - NCA) * 32; }
#pragma unroll
        for (int i = 0; i < 2; i++) {
            int u = tid + i * 256;
            int r = u >> 2, q = u & 3;
            int gr = rowBase + r;
            cp_async16(abase + r * 80 + q * 16,
                       src + (size_t)gr * st + col + q * 8, gr < NN ? 16 : 0);
        }
#pragma unroll
        for (int p = 0; p < 2; p++) {
            uint32_t bb = abase + ASZ + p * BSZ;
#pragma unroll
            for (int i = 0; i < 4; i++) {
                int u = tid + i * 256;
                int r = u >> 2, q = u & 3;
                cp_async16(bb + r * 80 + q * 16,
                           Bw + (size_t)r * K2 + p * KA5 + j * 32 + q * 8, 16);
            }
        }
        cp_commit();
    };

    uint32_t aOff = (uint32_t)((m0 + (lane & 15)) * 80 + (lane >> 4) * 16);
    uint32_t bOff = (uint32_t)((n0 + ((lane >> 4) << 3) + (lane & 7)) * 80 + ((lane >> 3) & 1) * 16);

    issue(0, 0);
    issue(1, 1);
    issue(2, 2);

    for (int j = 0; j < NCb; j++) {
        int s = j & (MST - 1);
        int younger = NCb - 1 - j;
        if (younger >= 2) cp_wait<2>();
        else if (younger == 1) cp_wait<1>();
        else cp_wait<0>();
        __syncthreads();
        uint32_t abase = sb + s * STB;
#pragma unroll
        for (int ks = 0; ks < 2; ks++) {
            uint32_t a[4][4];
#pragma unroll
            for (int tm = 0; tm < 4; tm++)
                ldsm4(a[tm][0], a[tm][1], a[tm][2], a[tm][3],
                      abase + aOff + tm * 1280 + ks * 32);
#pragma unroll
            for (int p = 0; p < 2; p++) {
                uint32_t bbase = abase + ASZ + p * BSZ;
                uint32_t b[4][4];
#pragma unroll
                for (int tb = 0; tb < 4; tb++)
                    ldsm4(b[tb][0], b[tb][1], b[tb][2], b[tb][3],
                          bbase + bOff + tb * 1280 + ks * 32);
#pragma unroll
                for (int tm = 0; tm < 4; tm++)
#pragma unroll
                    for (int tn = 0; tn < 8; tn++) {
                        uint32_t b0 = b[tn >> 1][(tn & 1) * 2];
                        uint32_t b1 = b[tn >> 1][(tn & 1) * 2 + 1];
                        asm volatile(
                            "mma.sync.aligned.m16n8k16.row.col.f32.f16.f16.f32 "
                            "{%0,%1,%2,%3}, {%4,%5,%6,%7}, {%8,%9}, {%0,%1,%2,%3};"
                            : "+f"(acc[tm][tn][0]), "+f"(acc[tm][tn][1]),
                              "+f"(acc[tm][tn][2]), "+f"(acc[tm][tn][3])
                            : "r"(a[tm][0]), "r"(a[tm][1]), "r"(a[tm][2]), "r"(a[tm][3]),
                              "r"(b0), "r"(b1));
                    }
            }
        }
        __syncthreads();
        if (j + 3 < NCb) issue(j + 3, (j + 3) & (MST - 1));
    }

#pragma unroll
    for (int tm = 0; tm < 4; tm++) {
        int r0 = rowBase + m0 + tm * 16 + t4;
        int r1 = r0 + 8;
#pragma unroll
        for (int tn = 0; tn < 8; tn++) {
            int col = n0 + tn * 8 + tq * 2;
            float bx = bias[col], by = bias[col + 1];
            if (r0 < NN)
                *(uint32_t*)(C + (size_t)r0 * 256 + col) =
                    hi_pack(fmaxf(acc[tm][tn][0] + bx, 0.f), fmaxf(acc[tm][tn][1] + by, 0.f));
            if (r1 < NN)
                *(uint32_t*)(C + (size_t)r1 * 256 + col) =
                    hi_pack(fmaxf(acc[tm][tn][2] + bx, 0.f), fmaxf(acc[tm][tn][3] + by, 0.f));
        }
    }
}

// ---------------- generic tail fp16 GEMM (CTA 128x128, warp 32x64) ----------------
__global__ void __launch_bounds__(256, 2)
mma_gemm(const __half* __restrict__ A, int KA,
         const __half* __restrict__ B, int K3,
         const float* __restrict__ bias, float* __restrict__ Cf,
         int ldc, int Nout, int relu,
         __half* __restrict__ Chl, int hlStride) {
    __shared__ __half As[2][128][40];
    __shared__ __half Bs[2][128][40];
    int tid = threadIdx.x;
    int wid = tid >> 5, lane = tid & 31;
    int t4 = lane >> 2, tq = lane & 3;
    int warp_m = wid & 3;
    int warp_n = wid >> 2;
    int rowBase = blockIdx.y * 128;
    int m0 = warp_m * 32, n0 = warp_n * 64;
    int NCb = KA / 32;
    int NC = 2 * NCb;

    float acc[2][8][4];
#pragma unroll
    for (int i = 0; i < 2; i++)
#pragma unroll
        for (int j = 0; j < 8; j++)
#pragma unroll
            for (int q = 0; q < 4; q++) acc[i][j][q] = 0.f;

    auto issue = [&](int cc, int s) {
        int ac = (cc < NCb) ? cc : cc - NCb;
#pragma unroll
        for (int i = 0; i < 2; i++) {
            int u = tid + i * 256;
            int r = u >> 2, q = u & 3;
            int gr = rowBase + r;
            cp_async16(smem_u32(&As[s][r][q * 8]),
                       A + (size_t)gr * KA + ac * 32 + q * 8, gr < NN ? 16 : 0);
            cp_async16(smem_u32(&Bs[s][r][q * 8]),
                       B + (size_t)r * K3 + cc * 32 + q * 8, 16);
        }
        cp_commit();
    };

    issue(0, 0);

    for (int c = 0; c < NC; c++) {
        int s = c & 1;
        if (c + 1 < NC) {
            issue(c + 1, s ^ 1);
            cp_wait<1>();
        } else {
            cp_wait<0>();
        }
        __syncthreads();
        const __half(*as)[40] = As[s];
        const __half(*bs)[40] = Bs[s];
#pragma unroll
        for (int ks = 0; ks < 2; ks++) {
            uint32_t a[2][4], b[8][2];
#pragma unroll
            for (int im = 0; im < 2; im++) {
                int rm = m0 + im * 16 + t4;
                int kc = ks * 16 + tq * 2;
                a[im][0] = *(const uint32_t*)&as[rm][kc];
                a[im][1] = *(const uint32_t*)&as[rm + 8][kc];
                a[im][2] = *(const uint32_t*)&as[rm][kc + 8];
                a[im][3] = *(const uint32_t*)&as[rm + 8][kc + 8];
            }
#pragma unroll
            for (int in = 0; in < 8; in++) {
                int rn = n0 + in * 8 + t4;
                int kc = ks * 16 + tq * 2;
                b[in][0] = *(const uint32_t*)&bs[rn][kc];
                b[in][1] = *(const uint32_t*)&bs[rn][kc + 8];
            }
#pragma unroll
            for (int im = 0; im < 2; im++)
#pragma unroll
                for (int in = 0; in < 8; in++) {
                    asm volatile(
                        "mma.sync.aligned.m16n8k16.row.col.f32.f16.f16.f32 "
                        "{%0,%1,%2,%3}, {%4,%5,%6,%7}, {%8,%9}, {%0,%1,%2,%3};"
                        : "+f"(acc[im][in][0]), "+f"(acc[im][in][1]),
                          "+f"(acc[im][in][2]), "+f"(acc[im][in][3])
                        : "r"(a[im][0]), "r"(a[im][1]), "r"(a[im][2]), "r"(a[im][3]),
                          "r"(b[in][0]), "r"(b[in][1]));
                }
        }
        __syncthreads();
    }

#pragma unroll
    for (int im = 0; im < 2; im++) {
        int gr0 = rowBase + m0 + im * 16 + t4;
#pragma unroll
        for (int in = 0; in < 8; in++) {
            int col = n0 + in * 8 + tq * 2;
            if (col >= Nout) continue;
            float bx = bias[col], by = bias[col + 1];
            float v0x = acc[im][in][0] + bx, v0y = acc[im][in][1] + by;
            float v1x = acc[im][in][2] + bx, v1y = acc[im][in][3] + by;
            if (relu) {
                v0x = fmaxf(v0x, 0.f); v0y = fmaxf(v0y, 0.f);
                v1x = fmaxf(v1x, 0.f); v1y = fmaxf(v1y, 0.f);
            }
            if (gr0 < NN) {
                if (Cf) *(float2*)&Cf[(size_t)gr0 * ldc + col] = make_float2(v0x, v0y);
                if (Chl) *(uint32_t*)(Chl + (size_t)gr0 * hlStride + col) = hi_pack(v0x, v0y);
            }
            if (gr0 + 8 < NN) {
                if (Cf) *(float2*)&Cf[(size_t)(gr0 + 8) * ldc + col] = make_float2(v1x, v1y);
                if (Chl) *(uint32_t*)(Chl + (size_t)(gr0 + 8) * hlStride + col) = hi_pack(v1x, v1y);
            }
        }
    }
}

// ---------------- tail kernels ----------------
// fused onset-pool (relation 0) + LayerNorm, fp16 in -> fp16 hi out, stride 128
__global__ void __launch_bounds__(256) pool_ln(const __half* __restrict__ hin,
                                               __half* __restrict__ dst,
                                               const float* __restrict__ g,
                                               const float* __restrict__ b) {
    int wid = threadIdx.x >> 5, lane = threadIdx.x & 31;
    int n = blockIdx.x * 8 + wid;
    if (n >= NN) return;
    int beg = g_off[n], end = g_off[n + 1];
    float acc[4];
    {
        uint2 v = __ldg((const uint2*)(hin + (size_t)n * 128 + lane * 4));
        float2 f0 = __half22float2(*(__half2*)&v.x);
        float2 f1 = __half22float2(*(__half2*)&v.y);
        acc[0] = f0.x; acc[1] = f0.y; acc[2] = f1.x; acc[3] = f1.y;
    }
    auto addv = [&](uint2 v) {
        float2 f0 = __half22float2(*(__half2*)&v.x);
        float2 f1 = __half22float2(*(__half2*)&v.y);
        acc[0] += f0.x; acc[1] += f0.y; acc[2] += f1.x; acc[3] += f1.y;
    };
    int e = beg;
    for (; e + 2 <= end; e += 2) {
        int s0 = __ldg(&g_list[e]);
        int s1 = __ldg(&g_list[e + 1]);
        uint2 v0 = __ldg((const uint2*)(hin + (size_t)s0 * 128 + lane * 4));
        uint2 v1 = __ldg((const uint2*)(hin + (size_t)s1 * 128 + lane * 4));
        addv(v0); addv(v1);
    }
    for (; e < end; e++) addv(__ldg((const uint2*)(hin + (size_t)__ldg(&g_list[e]) * 128 + lane * 4)));
    float inv = 1.0f / fmaxf((float)(end - beg), 1.0f);
#pragma unroll
    for (int i = 0; i < 4; i++) acc[i] *= inv;
    float s = acc[0] + acc[1] + acc[2] + acc[3];
    float q = acc[0] * acc[0] + acc[1] * acc[1] + acc[2] * acc[2] + acc[3] * acc[3];
#pragma unroll
    for (int o = 16; o; o >>= 1) {
        s += __shfl_xor_sync(0xffffffffu, s, o);
        q += __shfl_xor_sync(0xffffffffu, q, o);
    }
    float mu = s * (1.0f / 128.0f);
    float var = q * (1.0f / 128.0f) - mu * mu;
    float r = rsqrtf(var + 1e-5f);
    float4 gg = *(const float4*)&g[lane * 4];
    float4 bb = *(const float4*)&b[lane * 4];
    float ox = (acc[0] - mu) * r * gg.x + bb.x;
    float oy = (acc[1] - mu) * r * gg.y + bb.y;
    float oz = (acc[2] - mu) * r * gg.z + bb.z;
    float ow = (acc[3] - mu) * r * gg.w + bb.w;
    *(uint2*)(dst + (size_t)n * 128 + lane * 4) =
        make_uint2(hi_pack(ox, oy), hi_pack(oz, ow));
}

// LayerNorm (dim 128) fp32 in -> fp16 hi out, stride 128
__global__ void layernorm_hl(const float* __restrict__ in, __half* __restrict__ dst,
                             const float* __restrict__ g, const float* __restrict__ b) {
    int row = blockIdx.x * 8 + (threadIdx.x >> 5);
    int lane = threadIdx.x & 31;
    if (row >= NN) return;
    float4 v = *(const float4*)&in[(size_t)row * 128 + lane * 4];
    float s = v.x + v.y + v.z + v.w;
    float q = v.x * v.x + v.y * v.y + v.z * v.z + v.w * v.w;
#pragma unroll
    for (int o = 16; o; o >>= 1) {
        s += __shfl_xor_sync(0xffffffffu, s, o);
        q += __shfl_xor_sync(0xffffffffu, q, o);
    }
    float mu = s * (1.0f / 128.0f);
    float var = q * (1.0f / 128.0f) - mu * mu;
    float r = rsqrtf(var + 1e-5f);
    float4 gg = *(const float4*)&g[lane * 4];
    float4 bb = *(const float4*)&b[lane * 4];
    float ox = (v.x - mu) * r * gg.x + bb.x;
    float oy = (v.y - mu) * r * gg.y + bb.y;
    float oz = (v.z - mu) * r * gg.z + bb.z;
    float ow = (v.w - mu) * r * gg.w + bb.w;
    *(uint2*)(dst + (size_t)row * 128 + lane * 4) =
        make_uint2(hi_pack(ox, oy), hi_pack(oz, ow));
}

__global__ void bn_stats(const float* __restrict__ z) {
    __shared__ float ssum[256], ssq[256];
    int c = threadIdx.x & 63;
    int sub = threadIdx.x >> 6;
    float s = 0.f, q = 0.f;
    for (long r = (long)blockIdx.x * 4 + sub; r < NN; r += (long)gridDim.x * 4) {
        float v = z[r * 64 + c];
        s += v; q += v * v;
    }
    ssum[threadIdx.x] = s; ssq[threadIdx.x] = q;
    __syncthreads();
    if (sub == 0) {
        s = ssum[c] + ssum[64 + c] + ssum[128 + c] + ssum[192 + c];
        q = ssq[c] + ssq[64 + c] + ssq[128 + c] + ssq[192 + c];
        atomicAdd(&g_stats[c], s);
        atomicAdd(&g_stats[64 + c], q);
    }
}

__global__ void finalize_k(const float* __restrict__ z, const float* __restrict__ bn_g,
                           const float* __restrict__ bn_b, const float* __restrict__ cW2,
                           const float* __restrict__ cb2, float* __restrict__ out) {
    __shared__ float w[448], smu[64], sr[64], sg[64], sb[64], sb2[7];
    int tid = threadIdx.x;
    for (int i = tid; i < 448; i += blockDim.x) w[i] = cW2[i];
    if (tid < 64) {
        float mu = g_stats[tid] / (float)NN;
        float var = g_stats[64 + tid] / (float)NN - mu * mu;
        smu[tid] = mu;
        sr[tid] = rsqrtf(var + 1e-5f);
        sg[tid] = bn_g[tid];
        sb[tid] = bn_b[tid];
    }
    if (tid < 7) sb2[tid] = cb2[tid];
    __syncthreads();
    int row = blockIdx.x * blockDim.x + tid;
    if (row >= NN) return;
    float logits[7];
#pragma unroll
    for (int j = 0; j < 7; j++) logits[j] = sb2[j];
    for (int c = 0; c < 64; c += 4) {
        float4 v4 = *(const float4*)&z[(size_t)row * 64 + c];
        float vv[4] = {v4.x, v4.y, v4.z, v4.w};
#pragma unroll
        for (int u = 0; u < 4; u++) {
            int cc = c + u;
            float v = (vv[u] - smu[cc]) * sr[cc] * sg[cc] + sb[cc];
#pragma unroll
            for (int j = 0; j < 7; j++) logits[j] += v * w[cc * 7 + j];
        }
    }
    float m = logits[0];
#pragma unroll
    for (int j = 1; j < 7; j++) m = fmaxf(m, logits[j]);
    float ssum = 0.f;
#pragma unroll
    for (int j = 0; j < 7; j++) { logits[j] = expf(logits[j] - m); ssum += logits[j]; }
    float inv = 1.0f / ssum;
#pragma unroll
    for (int j = 0; j < 7; j++) out[(size_t)row * 7 + j] = logits[j] * inv;
}

// ---------------- host launcher ----------------
static inline int cdiv(long a, int b) { return (int)((a + b - 1) / b); }

extern "C" void kernel_launch(void* const* d_in, const int* in_sizes, int n_in,
                              void* d_out, int out_size) {
    const float* x = (const float*)d_in[0];
    const int* e0 = (const int*)d_in[1];
    const int* e1 = (const int*)d_in[2];
    const int* e2 = (const int*)d_in[3];
    const int* e3 = (const int*)d_in[4];
    const float* Wl0 = (const float*)d_in[5];
    const float* bl0 = (const float*)d_in[6];
    const float* Wr0 = (const float*)d_in[7];
    const float* Wl = (const float*)d_in[8];
    const float* bl = (const float*)d_in[9];
    const float* Wr = (const float*)d_in[10];
    const float* lin_W = (const float*)d_in[11];
    const float* lin_b = (const float*)d_in[12];
    const float* norm_g = (const float*)d_in[13];
    const float* norm_b = (const float*)d_in[14];
    const float* pW1 = (const float*)d_in[15];
    const float* pb1 = (const float*)d_in[16];
    const float* pln_g = (const float*)d_in[17];
    const float* pln_b = (const float*)d_in[18];
    const float* pW2 = (const float*)d_in[19];
    const float* pb2 = (const float*)d_in[20];
    const float* cW1 = (const float*)d_in[21];
    const float* cb1 = (const float*)d_in[22];
    const float* bn_g = (const float*)d_in[23];
    const float* bn_b = (const float*)d_in[24];
    const float* cW2 = (const float*)d_in[25];
    const float* cb2 = (const float*)d_in[26];
    float* out = (float*)d_out;

    float *ph, *ph2, *pbf;
    __half *pA, *pB, *phh, *pxh;
    __half (*pBbf)[(size_t)256 * 2560];
    __half (*pBt)[(size_t)128 * 512];
    float (*pbias)[256];
    int* pcur;
    cudaGetSymbolAddress((void**)&pA, g_AbfA);
    cudaGetSymbolAddress((void**)&pB, g_AbfB);
    cudaGetSymbolAddress((void**)&phh, g_hh);
    cudaGetSymbolAddress((void**)&pxh, g_xh);
    cudaGetSymbolAddress((void**)&pBbf, g_Bbf);
    cudaGetSymbolAddress((void**)&pBt, g_Bt);
    cudaGetSymbolAddress((void**)&pbf, g_bf);
    cudaGetSymbolAddress((void**)&pbias, g_bias);
    cudaGetSymbolAddress((void**)&ph, g_h);
    cudaGetSymbolAddress((void**)&ph2, g_h2);
    cudaGetSymbolAddress((void**)&pcur, g_cur);

    static bool attr_set = false;
    if (!attr_set) {
        cudaFuncSetAttribute(mma_main, cudaFuncAttributeMaxDynamicSharedMemorySize, MST * STB);
        attr_set = true;
    }

    const int T = 256;
    const int RB = cdiv(NN, 128);
    const dim3 TAIL_GRID(1, RB);
    const dim3 AGG_GRID(cdiv(NN, 8), 4);
    const dim3 EDGE_GRID4(cdiv(EE / 4, T), 4);

    // ---- CSR build + all weight prep ----
    zero_int<<<cdiv(4L * NN, T), T>>>(pcur, 4 * NN);
    hist_k<<<EDGE_GRID4, T>>>(e0, e1, e2, e3);
    scan_k<<<4, 1024>>>();
    fill_k<<<EDGE_GRID4, T>>>(e0, e1, e2, e3);
    prep_k<<<3426, 256>>>(Wl0, Wr0, bl0, Wl, Wr, bl, lin_W, pW1, pW2, pb2, cW1, cb1);
    convert_x<<<cdiv((long)NN * 32, T), T>>>(x);

    // ---- Layer 0 (D=128) ----
    aggregate_h<4><<<AGG_GRID, 256>>>(pxh, pA);
    mma_main<<<RB, 256, MST * STB>>>(pA, 512, pxh, 128, pBbf[0], pbias[0], phh, 20);

    // ---- Layer 1 (D=256) ----
    aggregate_h<8><<<AGG_GRID, 256>>>(phh, pB);
    mma_main<<<RB, 256, MST * STB>>>(pB, 1024, phh, 256, pBbf[1], pbias[1], phh, 40);

    // ---- Layer 2 ----
    aggregate_h<8><<<AGG_GRID, 256>>>(phh, pA);
    mma_main<<<RB, 256, MST * STB>>>(pA, 1024, phh, 256, pBbf[2], pbias[2], phh, 40);

    // ---- lin -> fp16 hi (pA, stride 128) ----
    mma_gemm<<<TAIL_GRID, 256>>>(phh, 256, pBt[0], 512, lin_b, nullptr, 128, 128, 0, pA, 128);

    // fused onset pooling + LN1 -> hi (pB, stride 128)
    pool_ln<<<cdiv(NN, 8), 256>>>(pA, pB, norm_g, norm_b);

    // pW1 (relu) -> fp32 g_h2
    mma_gemm<<<TAIL_GRID, 256>>>(pB, 128, pBt[1], 256, pb1, ph2, 128, 128, 1, nullptr, 0);
    // LN2 -> hi (pA, stride 128)
    layernorm_hl<<<cdiv(NN, 8), 256>>>(ph2, pA, pln_g, pln_b);
    // fused (pW2@cW1) GEMM: relu(h @ W' + b') -> fp32 g_h (ldc 64)
    mma_gemm<<<TAIL_GRID, 256>>>(pA, 128, pBt[2], 256, pbf, ph, 64, 64, 1, nullptr, 0);

    bn_stats<<<512, 256>>>(ph);
    finalize_k<<<cdiv(NN, 256), 256>>>(ph, bn_g, bn_b, cW2, cb2, out);
}